// round 13
// baseline (speedup 1.0000x reference)
#include <cuda_runtime.h>
#include <cstdint>

// MultiHashRouter — L2-persistence round, v2 (LDG.256).
// (Re-submit verbatim: previous round was a broker/container infra failure;
//  the kernel never executed.)
//
// ptxas on sm_100 requires .v8.b32/.v4.b64 with .L2::evict_last, so the
// input is read as ONE 32-byte ld.global.nc.L2::evict_last.v8.b32 per
// lane (lane j -> dims 8j..8j+7). This also halves the load count.
//
// Math (LAYER_ID=0, SALT=0):
//   r = XOR_{d=0..63} dim_value[d]*(d+1);  expert_ids[h] = (r&63)^h (distinct)
//   selected = [base, base^1], weights = 0.5
//   mask row: 0.5 at aligned column pair {base&~1, base|1}.
//
// Layout: 8-lane groups (4/warp); each group does 2 tokens (TOK_ITER=2),
// both LDG.256 front-batched. Warp = 8 tokens, block (256 thr) = 64 tokens,
// grid = 1024. Output: [sel (2N) | w (2N) | masks (64N)] float32 (verified).

#define HIDDEN_DIM 1024
#define N_EXPERTS  64
#define K_ACTIVE   2
#define TOK_ITER   2

struct F8 { float v[8]; };

__device__ __forceinline__ F8 ldg256_persist(const float* __restrict__ p) {
    F8 r;
    asm volatile(
        "ld.global.nc.L2::evict_last.v8.b32 {%0,%1,%2,%3,%4,%5,%6,%7}, [%8];"
        : "=f"(r.v[0]), "=f"(r.v[1]), "=f"(r.v[2]), "=f"(r.v[3]),
          "=f"(r.v[4]), "=f"(r.v[5]), "=f"(r.v[6]), "=f"(r.v[7])
        : "l"(p));
    return r;
}

__device__ __forceinline__ uint32_t dim_weighted(float h, uint32_t dplus1) {
    // dv = [h!=0] * ( (signbit<<3) | 4 | min(int(|h|),7) ), then * (d+1).
    uint32_t u = __float_as_uint(h);
    uint32_t mag = (uint32_t)(int)fminf(fabsf(h), 7.0f);    // FMNMX + F2I
    uint32_t code = ((u >> 28) & 8u) | 4u;                  // SHF + LOP3
    uint32_t dv = (h != 0.0f) ? (code | mag) : 0u;          // FSETP + SEL
    return dv * dplus1;                                     // IMAD
}

__global__ __launch_bounds__(256, 6)
void multihash_router_kernel(const float* __restrict__ hs,
                             float2* __restrict__ out_sel,   // [N]
                             float2* __restrict__ out_w,     // [N]
                             float4* __restrict__ out_mask,  // [N,16]
                             int n_tokens)
{
    const uint32_t lane = threadIdx.x & 31u;
    const uint32_t warp = threadIdx.x >> 5;
    const uint32_t g    = lane >> 3;          // lane-group 0..3
    const uint32_t j    = lane & 7u;          // 8-float chunk within token
    const uint32_t wb   = (blockIdx.x * 8u + warp) * 8u;    // warp's first token

    // ---- front-batched loads: one LDG.256 per lane per token ----
    F8 a[TOK_ITER];
    #pragma unroll
    for (int i = 0; i < TOK_ITER; i++) {
        uint32_t t = wb + 4u * i + g;
        uint32_t tc = min(t, (uint32_t)(n_tokens - 1));     // clamp (safe read)
        a[i] = ldg256_persist(hs + (size_t)tc * HIDDEN_DIM + 8u * j);
    }

    const uint32_t d1 = 8u * j + 1u;          // 1-based multiplier of dim 8j
    const float4 zero = make_float4(0.0f, 0.0f, 0.0f, 0.0f);

    #pragma unroll
    for (int i = 0; i < TOK_ITER; i++) {
        uint32_t r = 0u;
        #pragma unroll
        for (int k = 0; k < 8; k++)
            r ^= dim_weighted(a[i].v[k], d1 + (uint32_t)k);

        // butterfly XOR over each 8-lane group (groups are independent tokens)
        r ^= __shfl_xor_sync(0xFFFFFFFFu, r, 4);
        r ^= __shfl_xor_sync(0xFFFFFFFFu, r, 2);
        r ^= __shfl_xor_sync(0xFFFFFFFFu, r, 1);

        const uint32_t base = r & 63u;        // hash-0 expert; hash-1 = base^1
        const uint32_t hit  = base >> 2;      // float4 chunk (0..15) with pair

        const bool hiPair = (base & 2u) != 0u;
        const float lo = hiPair ? 0.0f : 0.5f;
        const float hi = hiPair ? 0.5f : 0.0f;
        const float4 hitv = make_float4(lo, lo, hi, hi);
        // lane owns contiguous float4 pair {2j, 2j+1} (cols 8j..8j+7)
        const float4 m0 = (hit == 2u * j)      ? hitv : zero;
        const float4 m1 = (hit == 2u * j + 1u) ? hitv : zero;

        const uint32_t t = wb + 4u * i + g;
        if (t < (uint32_t)n_tokens) {
            float4* mrow = out_mask + (size_t)t * (N_EXPERTS / 4);
            mrow[2u * j]      = m0;
            mrow[2u * j + 1u] = m1;
            if (j == 0u) {
                out_sel[t] = make_float2((float)base, (float)(base ^ 1u));
                out_w[t]   = make_float2(0.5f, 0.5f);
            }
        }
    }
}

extern "C" void kernel_launch(void* const* d_in, const int* in_sizes, int n_in,
                              void* d_out, int out_size)
{
    const float* hs = (const float*)d_in[0];
    int n_tokens = in_sizes[0] / HIDDEN_DIM;

    // Concat layout (verified): [selected (2N) | weights (2N) | masks (64N)].
    long long n = n_tokens;
    if ((long long)out_size < n * (2 * K_ACTIVE + N_EXPERTS)) {
        n = (long long)out_size / (2 * K_ACTIVE + N_EXPERTS);
        n_tokens = (int)n;
    }

    float* out = (float*)d_out;
    float2* out_sel  = (float2*)out;
    float2* out_w    = (float2*)(out + 2 * n);
    float4* out_mask = (float4*)(out + 4 * n);

    // 256 threads = 8 warps = 64 tokens per block
    const int blocks = (n_tokens + 63) / 64;
    multihash_router_kernel<<<blocks, 256>>>(hs, out_sel, out_w, out_mask,
                                             n_tokens);
}

// round 14
// speedup vs baseline: 1.0820x; 1.0820x over previous
#include <cuda_runtime.h>
#include <cstdint>

// MultiHashRouter — L2 contention experiment: input evict_last, output
// evict_first, both as 256-bit accesses (sm_100 requires .v8.b32 with
// L2 evict hints). Mask row per lane = 32B contiguous -> one STG.256.
//
// Math (LAYER_ID=0, SALT=0):
//   r = XOR_{d=0..63} dim_value[d]*(d+1);  expert_ids[h] = (r&63)^h (distinct)
//   selected = [base, base^1], weights = 0.5
//   mask row: 0.5 at aligned column pair {base&~1, base|1}.
//
// Layout: 8-lane groups (4/warp); each group does 2 tokens (TOK_ITER=2),
// both LDG.256 front-batched. Warp = 8 tokens, block (256 thr) = 64 tokens,
// grid = 1024. Output: [sel (2N) | w (2N) | masks (64N)] float32 (verified).

#define HIDDEN_DIM 1024
#define N_EXPERTS  64
#define K_ACTIVE   2
#define TOK_ITER   2

struct F8 { float v[8]; };

__device__ __forceinline__ F8 ldg256_persist(const float* __restrict__ p) {
    F8 r;
    asm volatile(
        "ld.global.nc.L2::evict_last.v8.b32 {%0,%1,%2,%3,%4,%5,%6,%7}, [%8];"
        : "=f"(r.v[0]), "=f"(r.v[1]), "=f"(r.v[2]), "=f"(r.v[3]),
          "=f"(r.v[4]), "=f"(r.v[5]), "=f"(r.v[6]), "=f"(r.v[7])
        : "l"(p));
    return r;
}

__device__ __forceinline__ void stg256_stream(float* __restrict__ p,
                                              float a0, float a1, float a2, float a3,
                                              float b0, float b1, float b2, float b3) {
    asm volatile(
        "st.global.L2::evict_first.v8.b32 [%0], {%1,%2,%3,%4,%5,%6,%7,%8};"
        :: "l"(p),
           "f"(a0), "f"(a1), "f"(a2), "f"(a3),
           "f"(b0), "f"(b1), "f"(b2), "f"(b3)
        : "memory");
}

__device__ __forceinline__ uint32_t dim_weighted(float h, uint32_t dplus1) {
    // dv = [h!=0] * ( (signbit<<3) | 4 | min(int(|h|),7) ), then * (d+1).
    uint32_t u = __float_as_uint(h);
    uint32_t mag = (uint32_t)(int)fminf(fabsf(h), 7.0f);    // FMNMX + F2I
    uint32_t code = ((u >> 28) & 8u) | 4u;                  // SHF + LOP3
    uint32_t dv = (h != 0.0f) ? (code | mag) : 0u;          // FSETP + SEL
    return dv * dplus1;                                     // IMAD
}

__global__ __launch_bounds__(256, 6)
void multihash_router_kernel(const float* __restrict__ hs,
                             float2* __restrict__ out_sel,   // [N]
                             float2* __restrict__ out_w,     // [N]
                             float*  __restrict__ out_mask,  // [N,64]
                             int n_tokens)
{
    const uint32_t lane = threadIdx.x & 31u;
    const uint32_t warp = threadIdx.x >> 5;
    const uint32_t g    = lane >> 3;          // lane-group 0..3
    const uint32_t j    = lane & 7u;          // 8-float chunk within token
    const uint32_t wb   = (blockIdx.x * 8u + warp) * 8u;    // warp's first token

    // ---- front-batched loads: one LDG.256 per lane per token ----
    F8 a[TOK_ITER];
    #pragma unroll
    for (int i = 0; i < TOK_ITER; i++) {
        uint32_t t = wb + 4u * i + g;
        uint32_t tc = min(t, (uint32_t)(n_tokens - 1));     // clamp (safe read)
        a[i] = ldg256_persist(hs + (size_t)tc * HIDDEN_DIM + 8u * j);
    }

    const uint32_t d1 = 8u * j + 1u;          // 1-based multiplier of dim 8j

    #pragma unroll
    for (int i = 0; i < TOK_ITER; i++) {
        uint32_t r = 0u;
        #pragma unroll
        for (int k = 0; k < 8; k++)
            r ^= dim_weighted(a[i].v[k], d1 + (uint32_t)k);

        // butterfly XOR over each 8-lane group (groups are independent tokens)
        r ^= __shfl_xor_sync(0xFFFFFFFFu, r, 4);
        r ^= __shfl_xor_sync(0xFFFFFFFFu, r, 2);
        r ^= __shfl_xor_sync(0xFFFFFFFFu, r, 1);

        const uint32_t base = r & 63u;        // hash-0 expert; hash-1 = base^1

        // lane owns cols 8j..8j+7; hit pair {base&~1, base|1} lies in one
        // aligned 4-col group (base>>2), i.e. in chunk 2j or 2j+1 of this lane.
        const uint32_t hit  = base >> 2;      // 4-col group index 0..15
        const bool hiPair = (base & 2u) != 0u;
        const float lo = hiPair ? 0.0f : 0.5f;
        const float hi = hiPair ? 0.5f : 0.0f;
        const bool in0 = (hit == 2u * j);
        const bool in1 = (hit == 2u * j + 1u);
        const float a0 = in0 ? lo : 0.0f, a1 = in0 ? lo : 0.0f;
        const float a2 = in0 ? hi : 0.0f, a3 = in0 ? hi : 0.0f;
        const float b0 = in1 ? lo : 0.0f, b1 = in1 ? lo : 0.0f;
        const float b2 = in1 ? hi : 0.0f, b3 = in1 ? hi : 0.0f;

        const uint32_t t = wb + 4u * i + g;
        if (t < (uint32_t)n_tokens) {
            stg256_stream(out_mask + (size_t)t * N_EXPERTS + 8u * j,
                          a0, a1, a2, a3, b0, b1, b2, b3);
            if (j == 0u) {
                out_sel[t] = make_float2((float)base, (float)(base ^ 1u));
                out_w[t]   = make_float2(0.5f, 0.5f);
            }
        }
    }
}

extern "C" void kernel_launch(void* const* d_in, const int* in_sizes, int n_in,
                              void* d_out, int out_size)
{
    const float* hs = (const float*)d_in[0];
    int n_tokens = in_sizes[0] / HIDDEN_DIM;

    // Concat layout (verified): [selected (2N) | weights (2N) | masks (64N)].
    long long n = n_tokens;
    if ((long long)out_size < n * (2 * K_ACTIVE + N_EXPERTS)) {
        n = (long long)out_size / (2 * K_ACTIVE + N_EXPERTS);
        n_tokens = (int)n;
    }

    float* out = (float*)d_out;
    float2* out_sel  = (float2*)out;
    float2* out_w    = (float2*)(out + 2 * n);
    float*  out_mask = out + 4 * n;

    // 256 threads = 8 warps = 64 tokens per block
    const int blocks = (n_tokens + 63) / 64;
    multihash_router_kernel<<<blocks, 256>>>(hs, out_sel, out_w, out_mask,
                                             n_tokens);
}